// round 4
// baseline (speedup 1.0000x reference)
#include <cuda_runtime.h>
#include <cuda_bf16.h>
#include <math.h>

// Problem constants
#define BB 2
#define TT 1024
#define VV 32000
#define EE 768
#define HH 12
#define HD 64
#define LL 4
#define NTOK (BB*TT)          // 2048
#define E3 (3*EE)             // 2304

// ----------------------------------------------------------------------------
// Scratch (device globals; no runtime allocation allowed)
// ----------------------------------------------------------------------------
__device__ float g_x   [NTOK*EE];
__device__ float g_h   [NTOK*EE];
__device__ float g_qkv [NTOK*E3];
__device__ float g_att [(size_t)BB*HH*TT*TT];
__device__ float g_y   [NTOK*EE];
__device__ float g_x2  [NTOK*EE];
__device__ float g_h2  [NTOK*EE];
__device__ float g_fc1 [NTOK*E3];
__device__ float g_xf  [NTOK*EE];
__device__ float g_rowloss[LL*NTOK];

// ----------------------------------------------------------------------------
// Embedding: x[n,e] = wte[tok[n],e] + wpe[n%T,e]
// ----------------------------------------------------------------------------
__global__ void embed_kernel(const int* __restrict__ tok,
                             const float* __restrict__ wte,
                             const float* __restrict__ wpe,
                             float* __restrict__ x)
{
    int idx = blockIdx.x * blockDim.x + threadIdx.x;
    if (idx >= NTOK*EE) return;
    int n = idx / EE;
    int e = idx - n*EE;
    int tk = tok[n];
    x[idx] = wte[(size_t)tk*EE + e] + wpe[(n & (TT-1))*EE + e];
}

// ----------------------------------------------------------------------------
// LayerNorm over E=768, one block per row, 256 threads (3 elems each)
// ----------------------------------------------------------------------------
__global__ __launch_bounds__(256) void ln_kernel(const float* __restrict__ x,
                                                 const float* __restrict__ w,
                                                 const float* __restrict__ b,
                                                 float* __restrict__ out)
{
    int n = blockIdx.x, tid = threadIdx.x;
    const float* row = x + (size_t)n*EE;
    float v[3];
    float s = 0.f;
    #pragma unroll
    for (int u = 0; u < 3; u++) { v[u] = row[tid + u*256]; s += v[u]; }
    __shared__ float sh[256];
    sh[tid] = s; __syncthreads();
    for (int off = 128; off; off >>= 1) { if (tid < off) sh[tid] += sh[tid+off]; __syncthreads(); }
    float mean = sh[0] * (1.f/EE);
    __syncthreads();
    float sq = 0.f;
    #pragma unroll
    for (int u = 0; u < 3; u++) { float d = v[u] - mean; sq += d*d; }
    sh[tid] = sq; __syncthreads();
    for (int off = 128; off; off >>= 1) { if (tid < off) sh[tid] += sh[tid+off]; __syncthreads(); }
    float rstd = rsqrtf(sh[0] * (1.f/EE) + 1e-5f);
    #pragma unroll
    for (int u = 0; u < 3; u++) {
        int e = tid + u*256;
        out[(size_t)n*EE + e] = (v[u] - mean) * rstd * w[e] + b[e];
    }
}

// ----------------------------------------------------------------------------
// Generic tiled SGEMM: C = A(MxK) @ B + bias (+res) (+gelu)
// TRANSB=0: B is KxN row-major.  TRANSB=1: B is NxK row-major (C=A@B^T).
// BM=BN=64, BK=16, 256 threads, 4x4 per thread. All dims multiples of 64/16.
// blockIdx.x -> m-tile, blockIdx.y -> n-tile (keeps B-tile reuse in L2 for
// the huge logits GEMM).
// ----------------------------------------------------------------------------
__device__ __forceinline__ float gelu_tanh(float x) {
    return 0.5f * x * (1.f + tanhf(0.7978845608028654f * (x + 0.044715f*x*x*x)));
}

template<int TRANSB, int ACT, int RES>
__global__ __launch_bounds__(256) void gemm64(const float* __restrict__ A,
                                              const float* __restrict__ B,
                                              const float* __restrict__ bias,
                                              const float* __restrict__ res,
                                              float* __restrict__ C,
                                              int M, int N, int K)
{
    __shared__ float As[16][64];
    __shared__ float Bs[16][64];
    int t  = threadIdx.x;
    int tx = t & 15, ty = t >> 4;
    int m0 = blockIdx.x * 64, n0 = blockIdx.y * 64;

    int ar = t >> 2;          // 0..63
    int ak = (t & 3) * 4;     // 0,4,8,12
    int bk = t >> 4;          // 0..15
    int bn = (t & 15) * 4;    // 0..60

    float acc[4][4] = {};

    for (int k0 = 0; k0 < K; k0 += 16) {
        float4 av = *(const float4*)(A + (size_t)(m0 + ar)*K + k0 + ak);
        As[ak+0][ar] = av.x; As[ak+1][ar] = av.y;
        As[ak+2][ar] = av.z; As[ak+3][ar] = av.w;
        if (TRANSB) {
            float4 bv = *(const float4*)(B + (size_t)(n0 + ar)*K + k0 + ak);
            Bs[ak+0][ar] = bv.x; Bs[ak+1][ar] = bv.y;
            Bs[ak+2][ar] = bv.z; Bs[ak+3][ar] = bv.w;
        } else {
            float4 bv = *(const float4*)(B + (size_t)(k0 + bk)*N + n0 + bn);
            *(float4*)&Bs[bk][bn] = bv;
        }
        __syncthreads();
        #pragma unroll
        for (int kk = 0; kk < 16; kk++) {
            float4 a = *(const float4*)&As[kk][ty*4];
            float4 b4 = *(const float4*)&Bs[kk][tx*4];
            float a_[4] = {a.x, a.y, a.z, a.w};
            float b_[4] = {b4.x, b4.y, b4.z, b4.w};
            #pragma unroll
            for (int i = 0; i < 4; i++)
                #pragma unroll
                for (int j = 0; j < 4; j++)
                    acc[i][j] = fmaf(a_[i], b_[j], acc[i][j]);
        }
        __syncthreads();
    }

    #pragma unroll
    for (int i = 0; i < 4; i++) {
        int row = m0 + ty*4 + i;
        #pragma unroll
        for (int j = 0; j < 4; j++) {
            int col = n0 + tx*4 + j;
            float v = acc[i][j];
            if (bias) v += bias[col];
            if (RES)  v += res[(size_t)row*N + col];
            if (ACT == 1) v = gelu_tanh(v);
            C[(size_t)row*N + col] = v;
        }
    }
}

// ----------------------------------------------------------------------------
// Attention scores: att[b,h,q,k] = sum_d q*k * 8.0   (ref multiplies by HD^0.5)
// Batched 64x64 tiles, K=64 fully resident.
// ----------------------------------------------------------------------------
__global__ __launch_bounds__(256) void attn_score(const float* __restrict__ qkv,
                                                  float* __restrict__ att)
{
    int bh = blockIdx.z, b = bh / HH, h = bh % HH;
    int q0 = blockIdx.y * 64, k0 = blockIdx.x * 64;
    __shared__ float Qs[64][64];   // [d][row]
    __shared__ float Ks[64][64];
    int t = threadIdx.x;
    const float* qbase = qkv + (size_t)(b*TT + q0)*E3 + h*HD;
    const float* kbase = qkv + (size_t)(b*TT + k0)*E3 + EE + h*HD;
    #pragma unroll
    for (int it = 0; it < 4; it++) {
        int f = it*256 + t;
        int row = f >> 4;
        int d4  = (f & 15) * 4;
        float4 qv = *(const float4*)(qbase + (size_t)row*E3 + d4);
        Qs[d4+0][row]=qv.x; Qs[d4+1][row]=qv.y; Qs[d4+2][row]=qv.z; Qs[d4+3][row]=qv.w;
        float4 kv = *(const float4*)(kbase + (size_t)row*E3 + d4);
        Ks[d4+0][row]=kv.x; Ks[d4+1][row]=kv.y; Ks[d4+2][row]=kv.z; Ks[d4+3][row]=kv.w;
    }
    __syncthreads();
    int tx = t & 15, ty = t >> 4;
    float acc[4][4] = {};
    #pragma unroll 8
    for (int d = 0; d < 64; d++) {
        float4 a = *(const float4*)&Qs[d][ty*4];
        float4 b4 = *(const float4*)&Ks[d][tx*4];
        float a_[4] = {a.x,a.y,a.z,a.w};
        float b_[4] = {b4.x,b4.y,b4.z,b4.w};
        #pragma unroll
        for (int i = 0; i < 4; i++)
            #pragma unroll
            for (int j = 0; j < 4; j++)
                acc[i][j] = fmaf(a_[i], b_[j], acc[i][j]);
    }
    float* obase = att + (size_t)bh*TT*TT;
    #pragma unroll
    for (int i = 0; i < 4; i++)
        #pragma unroll
        for (int j = 0; j < 4; j++)
            obase[(size_t)(q0 + ty*4 + i)*TT + k0 + tx*4 + j] = acc[i][j] * 8.0f;
}

// ----------------------------------------------------------------------------
// Softmax over last axis (1024), one block/row, values register-resident
// ----------------------------------------------------------------------------
__global__ __launch_bounds__(256) void softmax1024(float* __restrict__ att)
{
    size_t r = blockIdx.x;
    float* row = att + r*TT;
    int tid = threadIdx.x;
    float v[4];
    float m = -1e30f;
    #pragma unroll
    for (int u = 0; u < 4; u++) { v[u] = row[tid + u*256]; m = fmaxf(m, v[u]); }
    __shared__ float sh[256];
    sh[tid] = m; __syncthreads();
    for (int off = 128; off; off >>= 1) { if (tid < off) sh[tid] = fmaxf(sh[tid], sh[tid+off]); __syncthreads(); }
    m = sh[0]; __syncthreads();
    float s = 0.f;
    #pragma unroll
    for (int u = 0; u < 4; u++) { v[u] = expf(v[u] - m); s += v[u]; }
    sh[tid] = s; __syncthreads();
    for (int off = 128; off; off >>= 1) { if (tid < off) sh[tid] += sh[tid+off]; __syncthreads(); }
    float inv = 1.f / sh[0];
    #pragma unroll
    for (int u = 0; u < 4; u++) row[tid + u*256] = v[u] * inv;
}

// ----------------------------------------------------------------------------
// y[b,q,h,:] = att(1024x1024) @ V(1024x64) per (b,h)
// ----------------------------------------------------------------------------
__global__ __launch_bounds__(256) void attn_v(const float* __restrict__ att,
                                              const float* __restrict__ qkv,
                                              float* __restrict__ y)
{
    int bh = blockIdx.y, b = bh / HH, h = bh % HH;
    int q0 = blockIdx.x * 64;
    __shared__ float As[16][64];
    __shared__ float Vs[16][64];
    int t = threadIdx.x, tx = t & 15, ty = t >> 4;
    const float* abase = att + (size_t)bh*TT*TT + (size_t)q0*TT;
    const float* vbase = qkv + (size_t)(b*TT)*E3 + 2*EE + h*HD;
    int ar = t >> 2, ak = (t & 3) * 4;
    int vk = t >> 4, vd = (t & 15) * 4;
    float acc[4][4] = {};
    for (int k0 = 0; k0 < TT; k0 += 16) {
        float4 av = *(const float4*)(abase + (size_t)ar*TT + k0 + ak);
        As[ak+0][ar]=av.x; As[ak+1][ar]=av.y; As[ak+2][ar]=av.z; As[ak+3][ar]=av.w;
        float4 vv = *(const float4*)(vbase + (size_t)(k0 + vk)*E3 + vd);
        *(float4*)&Vs[vk][vd] = vv;
        __syncthreads();
        #pragma unroll
        for (int kk = 0; kk < 16; kk++) {
            float4 a = *(const float4*)&As[kk][ty*4];
            float4 b4 = *(const float4*)&Vs[kk][tx*4];
            float a_[4] = {a.x,a.y,a.z,a.w};
            float b_[4] = {b4.x,b4.y,b4.z,b4.w};
            #pragma unroll
            for (int i = 0; i < 4; i++)
                #pragma unroll
                for (int j = 0; j < 4; j++)
                    acc[i][j] = fmaf(a_[i], b_[j], acc[i][j]);
        }
        __syncthreads();
    }
    #pragma unroll
    for (int i = 0; i < 4; i++)
        #pragma unroll
        for (int j = 0; j < 4; j++)
            y[(size_t)(b*TT + q0 + ty*4 + i)*EE + h*HD + tx*4 + j] = acc[i][j];
}

// ----------------------------------------------------------------------------
// Per-row cross-entropy via online logsumexp over V=32000.
// rowloss[n] = -(logits[n, tgt[n]] - lse(logits[n,:]))
// ----------------------------------------------------------------------------
__global__ __launch_bounds__(256) void loss_rows(const float* __restrict__ logits,
                                                 const int* __restrict__ tgt,
                                                 float* __restrict__ rowloss)
{
    int n = blockIdx.x, tid = threadIdx.x;
    const float* row = logits + (size_t)n*VV;
    float m = -1e30f, s = 0.f;
    for (int i = tid; i < VV; i += 256) {
        float v = row[i];
        if (v > m) { s = s * expf(m - v) + 1.f; m = v; }
        else       { s += expf(v - m); }
    }
    __shared__ float sm[256], ss[256];
    sm[tid] = m; ss[tid] = s; __syncthreads();
    for (int off = 128; off; off >>= 1) {
        if (tid < off) {
            float m2 = sm[tid+off], s2 = ss[tid+off];
            float M = fmaxf(sm[tid], m2);
            ss[tid] = ss[tid]*expf(sm[tid]-M) + s2*expf(m2-M);
            sm[tid] = M;
        }
        __syncthreads();
    }
    if (tid == 0) {
        float lse = sm[0] + logf(ss[0]);
        rowloss[n] = -(row[tgt[n]] - lse);
    }
}

__global__ __launch_bounds__(256) void final_loss(const float* __restrict__ rowloss,
                                                  float* __restrict__ out)
{
    int tid = threadIdx.x;
    float s = 0.f;
    for (int i = tid; i < LL*NTOK; i += 256) s += rowloss[i];
    __shared__ float sh[256];
    sh[tid] = s; __syncthreads();
    for (int off = 128; off; off >>= 1) { if (tid < off) sh[tid] += sh[tid+off]; __syncthreads(); }
    if (tid == 0) out[0] = sh[0] * (1.f / NTOK);
}

// ----------------------------------------------------------------------------
// Launch
// ----------------------------------------------------------------------------
extern "C" void kernel_launch(void* const* d_in, const int* in_sizes, int n_in,
                              void* d_out, int out_size)
{
    const int* tok[LL+1];
    for (int i = 0; i <= LL; i++) tok[i] = (const int*)d_in[i];
    const float* wte    = (const float*)d_in[5];
    const float* wpe    = (const float*)d_in[6];
    const float* ln1_w  = (const float*)d_in[7];
    const float* ln1_b  = (const float*)d_in[8];
    const float* ln2_w  = (const float*)d_in[9];
    const float* ln2_b  = (const float*)d_in[10];
    const float* attn_w = (const float*)d_in[11];
    const float* attn_b = (const float*)d_in[12];
    const float* proj_w = (const float*)d_in[13];
    const float* proj_b = (const float*)d_in[14];
    const float* fc1_w  = (const float*)d_in[15];
    const float* fc1_b  = (const float*)d_in[16];
    const float* fc2_w  = (const float*)d_in[17];
    const float* fc2_b  = (const float*)d_in[18];
    float* out = (float*)d_out;

    float *px, *ph, *pqkv, *patt, *py, *px2, *ph2, *pfc1, *pxf, *prl;
    cudaGetSymbolAddress((void**)&px,   g_x);
    cudaGetSymbolAddress((void**)&ph,   g_h);
    cudaGetSymbolAddress((void**)&pqkv, g_qkv);
    cudaGetSymbolAddress((void**)&patt, g_att);
    cudaGetSymbolAddress((void**)&py,   g_y);
    cudaGetSymbolAddress((void**)&px2,  g_x2);
    cudaGetSymbolAddress((void**)&ph2,  g_h2);
    cudaGetSymbolAddress((void**)&pfc1, g_fc1);
    cudaGetSymbolAddress((void**)&pxf,  g_xf);
    cudaGetSymbolAddress((void**)&prl,  g_rowloss);

    for (int i = 0; i < LL; i++) {
        // x = wte[t_i] + wpe
        embed_kernel<<<(NTOK*EE + 255)/256, 256>>>(tok[i], wte, wpe, px);
        // h = LN1(x)
        ln_kernel<<<NTOK, 256>>>(px, ln1_w + i*EE, ln1_b + i*EE, ph);
        // qkv = h @ attn_w + attn_b
        gemm64<0,0,0><<<dim3(NTOK/64, E3/64), 256>>>(ph, attn_w + (size_t)i*EE*E3,
                                                     attn_b + i*E3, nullptr, pqkv,
                                                     NTOK, E3, EE);
        // att = (q @ k^T) * 8
        attn_score<<<dim3(TT/64, TT/64, BB*HH), 256>>>(pqkv, patt);
        // softmax
        softmax1024<<<BB*HH*TT, 256>>>(patt);
        // y = att @ v
        attn_v<<<dim3(TT/64, BB*HH), 256>>>(patt, pqkv, py);
        // x2 = x + y @ proj_w + proj_b
        gemm64<0,0,1><<<dim3(NTOK/64, EE/64), 256>>>(py, proj_w + (size_t)i*EE*EE,
                                                     proj_b + i*EE, px, px2,
                                                     NTOK, EE, EE);
        // h2 = LN2(x2)
        ln_kernel<<<NTOK, 256>>>(px2, ln2_w + i*EE, ln2_b + i*EE, ph2);
        // fc1 = gelu(h2 @ fc1_w + fc1_b)
        gemm64<0,1,0><<<dim3(NTOK/64, E3/64), 256>>>(ph2, fc1_w + (size_t)i*EE*E3,
                                                     fc1_b + i*E3, nullptr, pfc1,
                                                     NTOK, E3, EE);
        // xf = x2 + fc1 @ fc2_w + fc2_b
        gemm64<0,0,1><<<dim3(NTOK/64, EE/64), 256>>>(pfc1, fc2_w + (size_t)i*E3*EE,
                                                     fc2_b + i*EE, px2, pxf,
                                                     NTOK, EE, E3);
        // logits = xf @ wte^T  -> d_out (last layer's write survives)
        gemm64<1,0,0><<<dim3(NTOK/64, VV/64), 256>>>(pxf, wte, nullptr, nullptr, out,
                                                     NTOK, VV, EE);
        // per-row CE losses for this layer
        loss_rows<<<NTOK, 256>>>(out, tok[i+1], prl + i*NTOK);
    }
    if (out_size > NTOK*VV) {
        final_loss<<<1, 256>>>(prl, out + (size_t)NTOK*VV);
    }
}

// round 5
// speedup vs baseline: 1.0009x; 1.0009x over previous
#include <cuda_runtime.h>
#include <cuda_bf16.h>
#include <math.h>

// Problem constants
#define BB 2
#define TT 1024
#define VV 32000
#define EE 768
#define HH 12
#define HD 64
#define LL 4
#define NTOK (BB*TT)          // 2048
#define E3 (3*EE)             // 2304

// ----------------------------------------------------------------------------
// Scratch (device globals; no runtime allocation allowed)
// ----------------------------------------------------------------------------
__device__ float g_x   [NTOK*EE];
__device__ float g_h   [NTOK*EE];
__device__ float g_qkv [NTOK*E3];
__device__ float g_att [(size_t)BB*HH*TT*TT];
__device__ float g_y   [NTOK*EE];
__device__ float g_x2  [NTOK*EE];
__device__ float g_h2  [NTOK*EE];
__device__ float g_fc1 [NTOK*E3];
__device__ float g_xf  [NTOK*EE];
__device__ float g_rowloss[LL*NTOK];

// ----------------------------------------------------------------------------
// Embedding: x[n,e] = wte[tok[n],e] + wpe[n%T,e]
// ----------------------------------------------------------------------------
__global__ void embed_kernel(const int* __restrict__ tok,
                             const float* __restrict__ wte,
                             const float* __restrict__ wpe,
                             float* __restrict__ x)
{
    int idx = blockIdx.x * blockDim.x + threadIdx.x;
    if (idx >= NTOK*EE) return;
    int n = idx / EE;
    int e = idx - n*EE;
    int tk = tok[n];
    x[idx] = wte[(size_t)tk*EE + e] + wpe[(n & (TT-1))*EE + e];
}

// ----------------------------------------------------------------------------
// LayerNorm over E=768, one block per row, 256 threads (3 elems each)
// ----------------------------------------------------------------------------
__global__ __launch_bounds__(256) void ln_kernel(const float* __restrict__ x,
                                                 const float* __restrict__ w,
                                                 const float* __restrict__ b,
                                                 float* __restrict__ out)
{
    int n = blockIdx.x, tid = threadIdx.x;
    const float* row = x + (size_t)n*EE;
    float v[3];
    float s = 0.f;
    #pragma unroll
    for (int u = 0; u < 3; u++) { v[u] = row[tid + u*256]; s += v[u]; }
    __shared__ float sh[256];
    sh[tid] = s; __syncthreads();
    for (int off = 128; off; off >>= 1) { if (tid < off) sh[tid] += sh[tid+off]; __syncthreads(); }
    float mean = sh[0] * (1.f/EE);
    __syncthreads();
    float sq = 0.f;
    #pragma unroll
    for (int u = 0; u < 3; u++) { float d = v[u] - mean; sq += d*d; }
    sh[tid] = sq; __syncthreads();
    for (int off = 128; off; off >>= 1) { if (tid < off) sh[tid] += sh[tid+off]; __syncthreads(); }
    float rstd = rsqrtf(sh[0] * (1.f/EE) + 1e-5f);
    #pragma unroll
    for (int u = 0; u < 3; u++) {
        int e = tid + u*256;
        out[(size_t)n*EE + e] = (v[u] - mean) * rstd * w[e] + b[e];
    }
}

// ----------------------------------------------------------------------------
// Generic tiled SGEMM: C = A(MxK) @ B + bias (+res) (+gelu)
// TRANSB=0: B is KxN row-major.  TRANSB=1: B is NxK row-major (C=A@B^T).
// BM=BN=64, BK=16, 256 threads, 4x4 per thread. All dims multiples of 64/16.
// blockIdx.x -> m-tile, blockIdx.y -> n-tile (keeps B-tile reuse in L2 for
// the huge logits GEMM).
// ----------------------------------------------------------------------------
__device__ __forceinline__ float gelu_tanh(float x) {
    return 0.5f * x * (1.f + tanhf(0.7978845608028654f * (x + 0.044715f*x*x*x)));
}

template<int TRANSB, int ACT, int RES>
__global__ __launch_bounds__(256) void gemm64(const float* __restrict__ A,
                                              const float* __restrict__ B,
                                              const float* __restrict__ bias,
                                              const float* __restrict__ res,
                                              float* __restrict__ C,
                                              int M, int N, int K)
{
    __shared__ float As[16][64];
    __shared__ float Bs[16][64];
    int t  = threadIdx.x;
    int tx = t & 15, ty = t >> 4;
    int m0 = blockIdx.x * 64, n0 = blockIdx.y * 64;

    int ar = t >> 2;          // 0..63
    int ak = (t & 3) * 4;     // 0,4,8,12
    int bk = t >> 4;          // 0..15
    int bn = (t & 15) * 4;    // 0..60

    float acc[4][4] = {};

    for (int k0 = 0; k0 < K; k0 += 16) {
        float4 av = *(const float4*)(A + (size_t)(m0 + ar)*K + k0 + ak);
        As[ak+0][ar] = av.x; As[ak+1][ar] = av.y;
        As[ak+2][ar] = av.z; As[ak+3][ar] = av.w;
        if (TRANSB) {
            float4 bv = *(const float4*)(B + (size_t)(n0 + ar)*K + k0 + ak);
            Bs[ak+0][ar] = bv.x; Bs[ak+1][ar] = bv.y;
            Bs[ak+2][ar] = bv.z; Bs[ak+3][ar] = bv.w;
        } else {
            float4 bv = *(const float4*)(B + (size_t)(k0 + bk)*N + n0 + bn);
            *(float4*)&Bs[bk][bn] = bv;
        }
        __syncthreads();
        #pragma unroll
        for (int kk = 0; kk < 16; kk++) {
            float4 a = *(const float4*)&As[kk][ty*4];
            float4 b4 = *(const float4*)&Bs[kk][tx*4];
            float a_[4] = {a.x, a.y, a.z, a.w};
            float b_[4] = {b4.x, b4.y, b4.z, b4.w};
            #pragma unroll
            for (int i = 0; i < 4; i++)
                #pragma unroll
                for (int j = 0; j < 4; j++)
                    acc[i][j] = fmaf(a_[i], b_[j], acc[i][j]);
        }
        __syncthreads();
    }

    #pragma unroll
    for (int i = 0; i < 4; i++) {
        int row = m0 + ty*4 + i;
        #pragma unroll
        for (int j = 0; j < 4; j++) {
            int col = n0 + tx*4 + j;
            float v = acc[i][j];
            if (bias) v += bias[col];
            if (RES)  v += res[(size_t)row*N + col];
            if (ACT == 1) v = gelu_tanh(v);
            C[(size_t)row*N + col] = v;
        }
    }
}

// ----------------------------------------------------------------------------
// Attention scores: att[b,h,q,k] = sum_d q*k * 8.0   (ref multiplies by HD^0.5)
// Batched 64x64 tiles, K=64 fully resident.
// ----------------------------------------------------------------------------
__global__ __launch_bounds__(256) void attn_score(const float* __restrict__ qkv,
                                                  float* __restrict__ att)
{
    int bh = blockIdx.z, b = bh / HH, h = bh % HH;
    int q0 = blockIdx.y * 64, k0 = blockIdx.x * 64;
    __shared__ float Qs[64][64];   // [d][row]
    __shared__ float Ks[64][64];
    int t = threadIdx.x;
    const float* qbase = qkv + (size_t)(b*TT + q0)*E3 + h*HD;
    const float* kbase = qkv + (size_t)(b*TT + k0)*E3 + EE + h*HD;
    #pragma unroll
    for (int it = 0; it < 4; it++) {
        int f = it*256 + t;
        int row = f >> 4;
        int d4  = (f & 15) * 4;
        float4 qv = *(const float4*)(qbase + (size_t)row*E3 + d4);
        Qs[d4+0][row]=qv.x; Qs[d4+1][row]=qv.y; Qs[d4+2][row]=qv.z; Qs[d4+3][row]=qv.w;
        float4 kv = *(const float4*)(kbase + (size_t)row*E3 + d4);
        Ks[d4+0][row]=kv.x; Ks[d4+1][row]=kv.y; Ks[d4+2][row]=kv.z; Ks[d4+3][row]=kv.w;
    }
    __syncthreads();
    int tx = t & 15, ty = t >> 4;
    float acc[4][4] = {};
    #pragma unroll 8
    for (int d = 0; d < 64; d++) {
        float4 a = *(const float4*)&Qs[d][ty*4];
        float4 b4 = *(const float4*)&Ks[d][tx*4];
        float a_[4] = {a.x,a.y,a.z,a.w};
        float b_[4] = {b4.x,b4.y,b4.z,b4.w};
        #pragma unroll
        for (int i = 0; i < 4; i++)
            #pragma unroll
            for (int j = 0; j < 4; j++)
                acc[i][j] = fmaf(a_[i], b_[j], acc[i][j]);
    }
    float* obase = att + (size_t)bh*TT*TT;
    #pragma unroll
    for (int i = 0; i < 4; i++)
        #pragma unroll
        for (int j = 0; j < 4; j++)
            obase[(size_t)(q0 + ty*4 + i)*TT + k0 + tx*4 + j] = acc[i][j] * 8.0f;
}

// ----------------------------------------------------------------------------
// Softmax over last axis (1024), one block/row, values register-resident
// ----------------------------------------------------------------------------
__global__ __launch_bounds__(256) void softmax1024(float* __restrict__ att)
{
    size_t r = blockIdx.x;
    float* row = att + r*TT;
    int tid = threadIdx.x;
    float v[4];
    float m = -1e30f;
    #pragma unroll
    for (int u = 0; u < 4; u++) { v[u] = row[tid + u*256]; m = fmaxf(m, v[u]); }
    __shared__ float sh[256];
    sh[tid] = m; __syncthreads();
    for (int off = 128; off; off >>= 1) { if (tid < off) sh[tid] = fmaxf(sh[tid], sh[tid+off]); __syncthreads(); }
    m = sh[0]; __syncthreads();
    float s = 0.f;
    #pragma unroll
    for (int u = 0; u < 4; u++) { v[u] = expf(v[u] - m); s += v[u]; }
    sh[tid] = s; __syncthreads();
    for (int off = 128; off; off >>= 1) { if (tid < off) sh[tid] += sh[tid+off]; __syncthreads(); }
    float inv = 1.f / sh[0];
    #pragma unroll
    for (int u = 0; u < 4; u++) row[tid + u*256] = v[u] * inv;
}

// ----------------------------------------------------------------------------
// y[b,q,h,:] = att(1024x1024) @ V(1024x64) per (b,h)
// ----------------------------------------------------------------------------
__global__ __launch_bounds__(256) void attn_v(const float* __restrict__ att,
                                              const float* __restrict__ qkv,
                                              float* __restrict__ y)
{
    int bh = blockIdx.y, b = bh / HH, h = bh % HH;
    int q0 = blockIdx.x * 64;
    __shared__ float As[16][64];
    __shared__ float Vs[16][64];
    int t = threadIdx.x, tx = t & 15, ty = t >> 4;
    const float* abase = att + (size_t)bh*TT*TT + (size_t)q0*TT;
    const float* vbase = qkv + (size_t)(b*TT)*E3 + 2*EE + h*HD;
    int ar = t >> 2, ak = (t & 3) * 4;
    int vk = t >> 4, vd = (t & 15) * 4;
    float acc[4][4] = {};
    for (int k0 = 0; k0 < TT; k0 += 16) {
        float4 av = *(const float4*)(abase + (size_t)ar*TT + k0 + ak);
        As[ak+0][ar]=av.x; As[ak+1][ar]=av.y; As[ak+2][ar]=av.z; As[ak+3][ar]=av.w;
        float4 vv = *(const float4*)(vbase + (size_t)(k0 + vk)*E3 + vd);
        *(float4*)&Vs[vk][vd] = vv;
        __syncthreads();
        #pragma unroll
        for (int kk = 0; kk < 16; kk++) {
            float4 a = *(const float4*)&As[kk][ty*4];
            float4 b4 = *(const float4*)&Vs[kk][tx*4];
            float a_[4] = {a.x,a.y,a.z,a.w};
            float b_[4] = {b4.x,b4.y,b4.z,b4.w};
            #pragma unroll
            for (int i = 0; i < 4; i++)
                #pragma unroll
                for (int j = 0; j < 4; j++)
                    acc[i][j] = fmaf(a_[i], b_[j], acc[i][j]);
        }
        __syncthreads();
    }
    #pragma unroll
    for (int i = 0; i < 4; i++)
        #pragma unroll
        for (int j = 0; j < 4; j++)
            y[(size_t)(b*TT + q0 + ty*4 + i)*EE + h*HD + tx*4 + j] = acc[i][j];
}

// ----------------------------------------------------------------------------
// Per-row cross-entropy via online logsumexp over V=32000.
// rowloss[n] = -(logits[n, tgt[n]] - lse(logits[n,:]))
// ----------------------------------------------------------------------------
__global__ __launch_bounds__(256) void loss_rows(const float* __restrict__ logits,
                                                 const int* __restrict__ tgt,
                                                 float* __restrict__ rowloss)
{
    int n = blockIdx.x, tid = threadIdx.x;
    const float* row = logits + (size_t)n*VV;
    float m = -1e30f, s = 0.f;
    for (int i = tid; i < VV; i += 256) {
        float v = row[i];
        if (v > m) { s = s * expf(m - v) + 1.f; m = v; }
        else       { s += expf(v - m); }
    }
    __shared__ float sm[256], ss[256];
    sm[tid] = m; ss[tid] = s; __syncthreads();
    for (int off = 128; off; off >>= 1) {
        if (tid < off) {
            float m2 = sm[tid+off], s2 = ss[tid+off];
            float M = fmaxf(sm[tid], m2);
            ss[tid] = ss[tid]*expf(sm[tid]-M) + s2*expf(m2-M);
            sm[tid] = M;
        }
        __syncthreads();
    }
    if (tid == 0) {
        float lse = sm[0] + logf(ss[0]);
        rowloss[n] = -(row[tgt[n]] - lse);
    }
}

__global__ __launch_bounds__(256) void final_loss(const float* __restrict__ rowloss,
                                                  float* __restrict__ out)
{
    int tid = threadIdx.x;
    float s = 0.f;
    for (int i = tid; i < LL*NTOK; i += 256) s += rowloss[i];
    __shared__ float sh[256];
    sh[tid] = s; __syncthreads();
    for (int off = 128; off; off >>= 1) { if (tid < off) sh[tid] += sh[tid+off]; __syncthreads(); }
    if (tid == 0) out[0] = sh[0] * (1.f / NTOK);
}

// ----------------------------------------------------------------------------
// Launch
// ----------------------------------------------------------------------------
extern "C" void kernel_launch(void* const* d_in, const int* in_sizes, int n_in,
                              void* d_out, int out_size)
{
    const int* tok[LL+1];
    for (int i = 0; i <= LL; i++) tok[i] = (const int*)d_in[i];
    const float* wte    = (const float*)d_in[5];
    const float* wpe    = (const float*)d_in[6];
    const float* ln1_w  = (const float*)d_in[7];
    const float* ln1_b  = (const float*)d_in[8];
    const float* ln2_w  = (const float*)d_in[9];
    const float* ln2_b  = (const float*)d_in[10];
    const float* attn_w = (const float*)d_in[11];
    const float* attn_b = (const float*)d_in[12];
    const float* proj_w = (const float*)d_in[13];
    const float* proj_b = (const float*)d_in[14];
    const float* fc1_w  = (const float*)d_in[15];
    const float* fc1_b  = (const float*)d_in[16];
    const float* fc2_w  = (const float*)d_in[17];
    const float* fc2_b  = (const float*)d_in[18];
    float* out = (float*)d_out;

    float *px, *ph, *pqkv, *patt, *py, *px2, *ph2, *pfc1, *pxf, *prl;
    cudaGetSymbolAddress((void**)&px,   g_x);
    cudaGetSymbolAddress((void**)&ph,   g_h);
    cudaGetSymbolAddress((void**)&pqkv, g_qkv);
    cudaGetSymbolAddress((void**)&patt, g_att);
    cudaGetSymbolAddress((void**)&py,   g_y);
    cudaGetSymbolAddress((void**)&px2,  g_x2);
    cudaGetSymbolAddress((void**)&ph2,  g_h2);
    cudaGetSymbolAddress((void**)&pfc1, g_fc1);
    cudaGetSymbolAddress((void**)&pxf,  g_xf);
    cudaGetSymbolAddress((void**)&prl,  g_rowloss);

    for (int i = 0; i < LL; i++) {
        // x = wte[t_i] + wpe
        embed_kernel<<<(NTOK*EE + 255)/256, 256>>>(tok[i], wte, wpe, px);
        // h = LN1(x)
        ln_kernel<<<NTOK, 256>>>(px, ln1_w + i*EE, ln1_b + i*EE, ph);
        // qkv = h @ attn_w + attn_b
        gemm64<0,0,0><<<dim3(NTOK/64, E3/64), 256>>>(ph, attn_w + (size_t)i*EE*E3,
                                                     attn_b + i*E3, nullptr, pqkv,
                                                     NTOK, E3, EE);
        // att = (q @ k^T) * 8
        attn_score<<<dim3(TT/64, TT/64, BB*HH), 256>>>(pqkv, patt);
        // softmax
        softmax1024<<<BB*HH*TT, 256>>>(patt);
        // y = att @ v
        attn_v<<<dim3(TT/64, BB*HH), 256>>>(patt, pqkv, py);
        // x2 = x + y @ proj_w + proj_b
        gemm64<0,0,1><<<dim3(NTOK/64, EE/64), 256>>>(py, proj_w + (size_t)i*EE*EE,
                                                     proj_b + i*EE, px, px2,
                                                     NTOK, EE, EE);
        // h2 = LN2(x2)
        ln_kernel<<<NTOK, 256>>>(px2, ln2_w + i*EE, ln2_b + i*EE, ph2);
        // fc1 = gelu(h2 @ fc1_w + fc1_b)
        gemm64<0,1,0><<<dim3(NTOK/64, E3/64), 256>>>(ph2, fc1_w + (size_t)i*EE*E3,
                                                     fc1_b + i*E3, nullptr, pfc1,
                                                     NTOK, E3, EE);
        // xf = x2 + fc1 @ fc2_w + fc2_b
        gemm64<0,0,1><<<dim3(NTOK/64, EE/64), 256>>>(pfc1, fc2_w + (size_t)i*E3*EE,
                                                     fc2_b + i*EE, px2, pxf,
                                                     NTOK, EE, E3);
        // logits = xf @ wte^T  -> d_out (last layer's write survives)
        gemm64<1,0,0><<<dim3(NTOK/64, VV/64), 256>>>(pxf, wte, nullptr, nullptr, out,
                                                     NTOK, VV, EE);
        // per-row CE losses for this layer
        loss_rows<<<NTOK, 256>>>(out, tok[i+1], prl + i*NTOK);
    }
    if (out_size > NTOK*VV) {
        final_loss<<<1, 256>>>(prl, out + (size_t)NTOK*VV);
    }
}